// round 8
// baseline (speedup 1.0000x reference)
#include <cuda_runtime.h>

#define TSTEPS 65536
#define DTF (5.0f/60.0f)

// 8 MB log of h_t (state at the START of step t) for the observer pass.
__device__ float g_hs[(size_t)TSTEPS * 32];

typedef unsigned long long ull;

static __device__ __forceinline__ ull pk2(float lo, float hi) {
    ull r; asm("mov.b64 %0, {%1,%2};" : "=l"(r) : "f"(lo), "f"(hi)); return r;
}
static __device__ __forceinline__ float2 upk2(ull v) {
    float2 r; asm("mov.b64 {%0,%1}, %2;" : "=f"(r.x), "=f"(r.y) : "l"(v)); return r;
}
// Packed fp32x2 FMA / ADD (Blackwell): 2 fp32 ops per instruction.
static __device__ __forceinline__ ull ffma2(ull a, ull b, ull c) {
    ull d; asm("fma.rn.f32x2 %0, %1, %2, %3;" : "=l"(d) : "l"(a), "l"(b), "l"(c)); return d;
}
static __device__ __forceinline__ ull fadd2(ull a, ull b) {
    ull d; asm("add.rn.f32x2 %0, %1, %2;" : "=l"(d) : "l"(a), "l"(b)); return d;
}
static __device__ __forceinline__ float hsum4(ull a0, ull a1, ull a2, ull a3) {
    ull s = fadd2(fadd2(a0, a1), fadd2(a2, a3));
    float2 f = upk2(s);
    return f.x + f.y;
}

static __device__ __forceinline__ float silu_f(float x) {
    float e = __expf(-x);
    return __fdividef(x, 1.0f + e);
}
static __device__ __forceinline__ float tanh_f(float x) {
    float e = __expf(2.0f * x);
    return 1.0f - __fdividef(2.0f, e + 1.0f);
}

__global__ __launch_bounds__(128, 1)
void node_scan_kernel(const float* __restrict__ U, const float* __restrict__ h0,
                      const float* __restrict__ W1, const float* __restrict__ b1,
                      const float* __restrict__ W2, const float* __restrict__ b2,
                      const float* __restrict__ W3, const float* __restrict__ b3,
                      float* __restrict__ out)
{
    __shared__ __align__(16) float sz1[128];
    __shared__ __align__(16) float sz2[128];
    __shared__ __align__(16) float sp[128];     // layer-3 partials (cross-warp)
    __shared__ __align__(16) float sxg[4][32];  // per-warp private h-broadcast
    __shared__ __align__(16) float su[4][8];    // per-warp private u
    __shared__ float sW1u[8 * 128];             // u-rows of W1
    // L1 h-weights, ulonglong2-paired: entry [m2*128 + j] holds (w1h[2m2], w1h[2m2+1])
    // 16-byte thread stride -> LDS.128 conflict-free.
    __shared__ __align__(16) ulonglong2 sW1q[8 * 128];     // 16 KB
    // L3 weights: entry [(m2*4 + g)*32 + lane] holds (w3p[2m2], w3p[2m2+1])
    __shared__ __align__(16) ulonglong2 sW3q[8 * 4 * 32];  // 16 KB

    const int j    = threadIdx.x;
    const int lane = j & 31;
    const int g    = j >> 5;

    // ---- L1 h-weights into shared (paired layout) ----
#pragma unroll
    for (int m2 = 0; m2 < 8; m2++) {
        ulonglong2 w;
        w.x = pk2(W1[(4*m2 + 0)*128 + j], W1[(4*m2 + 1)*128 + j]);
        w.y = pk2(W1[(4*m2 + 2)*128 + j], W1[(4*m2 + 3)*128 + j]);
        sW1q[m2*128 + j] = w;
    }
    const float b1j = b1[j];

    // ---- L2 weights stay register-resident (the big block) ----
    ull w2p[64];
#pragma unroll
    for (int m = 0; m < 64; m++)
        w2p[m] = pk2(W2[(2*m)*128 + j], W2[(2*m+1)*128 + j]);
    const float b2j = b2[j];

    // ---- L3 weights into shared (paired layout) ----
#pragma unroll
    for (int m2 = 0; m2 < 8; m2++) {
        ulonglong2 w;
        w.x = pk2(W3[(32*g + 4*m2 + 0)*32 + lane], W3[(32*g + 4*m2 + 1)*32 + lane]);
        w.y = pk2(W3[(32*g + 4*m2 + 2)*32 + lane], W3[(32*g + 4*m2 + 3)*32 + lane]);
        sW3q[(m2*4 + g)*32 + lane] = w;
    }
    const float b3l = b3[lane];

    // u-rows of W1 into shared (used once per step for zu)
#pragma unroll
    for (int m = j; m < 8 * 128; m += 128) sW1u[m] = W1[32*128 + m];

    // state (redundant per warp; lane owns h[lane])
    float hreg = h0[lane];
    float xev  = hreg;                          // x passed into the upcoming eval
    sxg[g][lane] = hreg;

    // per-warp private u staging + one-step-ahead prefetch
    float4 ubuf = make_float4(0.f, 0.f, 0.f, 0.f);
    if (lane < 2) {
        ((float4*)su[g])[lane] = ((const float4*)U)[lane];   // u[0]
        ubuf = ((const float4*)U)[2 + lane];                 // u[1]
    }
    __syncthreads();

    // zu_j = b1[j] + u . W1u[:,j]  (recomputed once per step)
    float zu = b1j;
#pragma unroll
    for (int m = 0; m < 8; m++) zu = fmaf(su[g][m], sW1u[m*128 + j], zu);

    float accK = 0.0f;

#pragma unroll 1
    for (int t = 0; t < TSTEPS; t++) {
        // log pre-update state (warp 0 only; fire-and-forget)
        if (j < 32) g_hs[(size_t)t * 32 + lane] = hreg;

#pragma unroll
        for (int s = 0; s < 4; s++) {
            // ---- layer 1 (h-part): 32 -> 128, + zu, silu ----
            ull a0 = 0, a1 = 0, a2 = 0, a3 = 0;
            const ulonglong2* xv = (const ulonglong2*)sxg[g];   // 8 entries
#pragma unroll
            for (int m = 0; m < 4; m++) {
                ulonglong2 p  = xv[2*m];
                ulonglong2 q  = xv[2*m + 1];
                ulonglong2 wA = sW1q[(2*m)*128 + j];     // (w1h[4m],   w1h[4m+1])
                ulonglong2 wB = sW1q[(2*m + 1)*128 + j]; // (w1h[4m+2], w1h[4m+3])
                a0 = ffma2(p.x, wA.x, a0);
                a1 = ffma2(p.y, wA.y, a1);
                a2 = ffma2(q.x, wB.x, a2);
                a3 = ffma2(q.y, wB.y, a3);
            }
            float z = zu + hsum4(a0, a1, a2, a3);
            sz1[j] = silu_f(z);
            __syncthreads();                                    // BAR_A (all-to-all)

            // ---- layer 2: 128 -> 128, silu ----
            a0 = a1 = a2 = a3 = 0;
            const ulonglong2* zv = (const ulonglong2*)sz1;      // 32 entries
#pragma unroll
            for (int m = 0; m < 16; m++) {
                ulonglong2 p = zv[2*m];
                ulonglong2 q = zv[2*m + 1];
                a0 = ffma2(p.x, w2p[4*m + 0], a0);
                a1 = ffma2(p.y, w2p[4*m + 1], a1);
                a2 = ffma2(q.x, w2p[4*m + 2], a2);
                a3 = ffma2(q.y, w2p[4*m + 3], a3);
            }
            z = b2j + hsum4(a0, a1, a2, a3);
            sz2[j] = silu_f(z);
            __syncwarp();          // layer-3 inputs are own-warp's sz2 chunk only

            // ---- layer 3 partials over own chunk: rows [32g, 32g+32) ----
            a0 = 0; a1 = 0;
            const ulonglong2* z2v = (const ulonglong2*)(sz2 + 32*g);  // 8 entries
#pragma unroll
            for (int m = 0; m < 8; m++) {
                ulonglong2 p  = z2v[m];
                ulonglong2 wC = sW3q[(m*4 + g)*32 + lane];  // (w3p[2m], w3p[2m+1])
                a0 = ffma2(p.x, wC.x, a0);
                a1 = ffma2(p.y, wC.y, a1);
            }
            {
                float2 f = upk2(fadd2(a0, a1));
                sp[j] = f.x + f.y;
            }
            __syncthreads();                                    // BAR_B (cross-warp)

            // ---- redundant reduce + RK4 update (every warp, lane owns state) ----
            float drift = b3l + ((sp[lane] + sp[lane + 32]) + (sp[lane + 64] + sp[lane + 96]));
            float dyn   = 0.02f * drift - 0.1f * xev;
            if (s == 0)      { accK  = dyn;        xev = hreg + (0.5f * DTF) * dyn; }
            else if (s == 1) { accK += 2.0f * dyn; xev = hreg + (0.5f * DTF) * dyn; }
            else if (s == 2) { accK += 2.0f * dyn; xev = hreg + DTF * dyn; }
            else {
                accK += dyn;
                hreg = tanh_f(hreg + (DTF / 6.0f) * accK);
                xev  = hreg;
                if (lane < 2) {
                    ((float4*)su[g])[lane] = ubuf;              // u[t+1] in place
                    int nt = (t + 2 < TSTEPS) ? (t + 2) : (TSTEPS - 1);
                    ubuf = ((const float4*)U)[2*nt + lane];     // prefetch u[t+2]
                }
            }
            sxg[g][lane] = xev;
            __syncwarp();

            if (s == 3) {   // refresh zu for the next step (su just updated)
                float zz = b1j;
#pragma unroll
                for (int m = 0; m < 8; m++) zz = fmaf(su[g][m], sW1u[m*128 + j], zz);
                zu = zz;
            }
        }
    }

    if (j < 32) out[3 * TSTEPS + j] = hreg;   // h_last
}

// Observer pass: d/t/c = h_t @ W{d,t,c} + b — embarrassingly parallel over t.
__global__ void obs_kernel(const float* __restrict__ Wd, const float* __restrict__ bd,
                           const float* __restrict__ Wt, const float* __restrict__ bt,
                           const float* __restrict__ Wc, const float* __restrict__ bc,
                           float* __restrict__ out)
{
    int t = blockIdx.x * blockDim.x + threadIdx.x;
    if (t >= TSTEPS) return;
    const float4* h4 = (const float4*)(g_hs + (size_t)t * 32);
    float ad = 0.f, at = 0.f, ac = 0.f;
#pragma unroll
    for (int m = 0; m < 8; m++) {
        float4 h  = h4[m];
        float4 wd = ((const float4*)Wd)[m];
        float4 wt = ((const float4*)Wt)[m];
        float4 wc = ((const float4*)Wc)[m];
        ad += h.x*wd.x + h.y*wd.y + h.z*wd.z + h.w*wd.w;
        at += h.x*wt.x + h.y*wt.y + h.z*wt.z + h.w*wt.w;
        ac += h.x*wc.x + h.y*wc.y + h.z*wc.z + h.w*wc.w;
    }
    out[t]              = ad + bd[0];
    out[TSTEPS + t]     = at + bt[0];
    out[2 * TSTEPS + t] = ac + bc[0];
}

// ncu: captured global launch index 5 = our index 3 (+2 harness offset).
// Dummies first so node_scan_kernel sits at our index 3.
__global__ void dummy_kernel() {}

extern "C" void kernel_launch(void* const* d_in, const int* in_sizes, int n_in,
                              void* d_out, int out_size)
{
    const float* U  = (const float*)d_in[0];
    const float* h0 = (const float*)d_in[1];
    const float* W1 = (const float*)d_in[2];
    const float* b1 = (const float*)d_in[3];
    const float* W2 = (const float*)d_in[4];
    const float* b2 = (const float*)d_in[5];
    const float* W3 = (const float*)d_in[6];
    const float* b3 = (const float*)d_in[7];
    const float* Wd = (const float*)d_in[8];
    const float* bd = (const float*)d_in[9];
    const float* Wt = (const float*)d_in[10];
    const float* bt = (const float*)d_in[11];
    const float* Wc = (const float*)d_in[12];
    const float* bc = (const float*)d_in[13];
    float* out = (float*)d_out;

    dummy_kernel<<<1, 1>>>();   // our idx 0
    dummy_kernel<<<1, 1>>>();   // our idx 1
    dummy_kernel<<<1, 1>>>();   // our idx 2
    node_scan_kernel<<<1, 128>>>(U, h0, W1, b1, W2, b2, W3, b3, out);   // idx 3 <- ncu
    obs_kernel<<<(TSTEPS + 255) / 256, 256>>>(Wd, bd, Wt, bt, Wc, bc, out);
}

// round 9
// speedup vs baseline: 1.1349x; 1.1349x over previous
#include <cuda_runtime.h>

#define TSTEPS 65536
#define DTF (5.0f/60.0f)

// 8 MB log of h_t (state at the START of step t) for the observer pass.
__device__ float g_hs[(size_t)TSTEPS * 32];

typedef unsigned long long ull;

static __device__ __forceinline__ ull pk2(float lo, float hi) {
    ull r; asm("mov.b64 %0, {%1,%2};" : "=l"(r) : "f"(lo), "f"(hi)); return r;
}
static __device__ __forceinline__ float2 upk2(ull v) {
    float2 r; asm("mov.b64 {%0,%1}, %2;" : "=f"(r.x), "=f"(r.y) : "l"(v)); return r;
}
// Packed fp32x2 FMA / ADD (Blackwell): 2 fp32 ops per instruction.
static __device__ __forceinline__ ull ffma2(ull a, ull b, ull c) {
    ull d; asm("fma.rn.f32x2 %0, %1, %2, %3;" : "=l"(d) : "l"(a), "l"(b), "l"(c)); return d;
}
static __device__ __forceinline__ ull fadd2(ull a, ull b) {
    ull d; asm("add.rn.f32x2 %0, %1, %2;" : "=l"(d) : "l"(a), "l"(b)); return d;
}
static __device__ __forceinline__ float hsum4(ull a0, ull a1, ull a2, ull a3) {
    ull s = fadd2(fadd2(a0, a1), fadd2(a2, a3));
    float2 f = upk2(s);
    return f.x + f.y;
}

static __device__ __forceinline__ float silu_f(float x) {
    float e = __expf(-x);
    return __fdividef(x, 1.0f + e);
}
static __device__ __forceinline__ float tanh_f(float x) {
    float e = __expf(2.0f * x);
    return 1.0f - __fdividef(2.0f, e + 1.0f);
}

__global__ __launch_bounds__(256, 1)
void node_scan_kernel(const float* __restrict__ U, const float* __restrict__ h0,
                      const float* __restrict__ W1, const float* __restrict__ b1,
                      const float* __restrict__ W2, const float* __restrict__ b2,
                      const float* __restrict__ W3, const float* __restrict__ b3,
                      float* __restrict__ out)
{
    __shared__ __align__(16) float sz1[128];
    __shared__ __align__(16) float sz2[128];
    __shared__ __align__(16) float sp[128];     // layer-3 partials (cross-warp)
    __shared__ __align__(16) float spz2[128];   // aux L2 upper-half partials
    __shared__ __align__(16) float sxg[4][32];  // per-warp private h-broadcast (main)
    __shared__ __align__(16) float su[4][8];    // per-warp private u (main)
    __shared__ float sW1u[8 * 128];             // u-rows of W1

    const int tid  = threadIdx.x;
    const int j    = tid & 127;                 // output index (both groups)
    const int lane = tid & 31;
    const int g    = (tid >> 5) & 3;            // main warp id 0-3
    const bool is_main = (tid < 128);

    // u-rows of W1 into shared (all 256 threads)
#pragma unroll
    for (int m = tid; m < 8 * 128; m += 256) sW1u[m] = W1[32*128 + m];

    // ---- register-resident weights ----
    // main: w1h (L1 h-rows), w2p_lo (W2 rows 0..63), w3p, biases, state
    // aux : w2p_hi (W2 rows 64..127)
    ull w1h[16];
    ull w2half[32];
    ull w3p[16];
    float b1j = 0.f, b2j = 0.f, b3l = 0.f;
    float hreg = 0.f, xev = 0.f;
    float4 ubuf = make_float4(0.f, 0.f, 0.f, 0.f);

    if (is_main) {
#pragma unroll
        for (int m = 0; m < 16; m++)
            w1h[m] = pk2(W1[(2*m)*128 + j], W1[(2*m+1)*128 + j]);
        b1j = b1[j];
#pragma unroll
        for (int m = 0; m < 32; m++)        // k in [0,64)
            w2half[m] = pk2(W2[(2*m)*128 + j], W2[(2*m+1)*128 + j]);
        b2j = b2[j];
#pragma unroll
        for (int m = 0; m < 16; m++)
            w3p[m] = pk2(W3[(32*g + 2*m)*32 + lane], W3[(32*g + 2*m + 1)*32 + lane]);
        b3l = b3[lane];

        hreg = h0[lane];
        xev  = hreg;
        sxg[g][lane] = hreg;
        if (lane < 2) {
            ((float4*)su[g])[lane] = ((const float4*)U)[lane];   // u[0]
            ubuf = ((const float4*)U)[2 + lane];                 // u[1]
        }
    } else {
#pragma unroll
        for (int m = 0; m < 32; m++)        // k in [64,128)
            w2half[m] = pk2(W2[(64 + 2*m)*128 + j], W2[(65 + 2*m)*128 + j]);
    }
    __syncthreads();

    // zu_j = b1[j] + u . W1u[:,j]  (main only; recomputed once per step)
    float zu = 0.f;
    if (is_main) {
        zu = b1j;
#pragma unroll
        for (int m = 0; m < 8; m++) zu = fmaf(su[g][m], sW1u[m*128 + j], zu);
    }

    float accK = 0.0f;

#pragma unroll 1
    for (int t = 0; t < TSTEPS; t++) {
        if (tid < 32) g_hs[(size_t)t * 32 + lane] = hreg;   // fire-and-forget log

#pragma unroll
        for (int s = 0; s < 4; s++) {
            if (is_main) {
                // ---- layer 1 (h-part): 32 -> 128, + zu, silu ----
                ull a0 = 0, a1 = 0, a2 = 0, a3 = 0;
                const ulonglong2* xv = (const ulonglong2*)sxg[g];   // 8 entries
#pragma unroll
                for (int m = 0; m < 4; m++) {
                    ulonglong2 p = xv[2*m];
                    ulonglong2 q = xv[2*m + 1];
                    a0 = ffma2(p.x, w1h[4*m + 0], a0);
                    a1 = ffma2(p.y, w1h[4*m + 1], a1);
                    a2 = ffma2(q.x, w1h[4*m + 2], a2);
                    a3 = ffma2(q.y, w1h[4*m + 3], a3);
                }
                float z = zu + hsum4(a0, a1, a2, a3);
                sz1[j] = silu_f(z);
            }
            __syncthreads();                                    // BAR_A

            // ---- layer 2 K-split: both groups compute their half ----
            ull a0 = 0, a1 = 0, a2 = 0, a3 = 0;
            {
                const ulonglong2* zv = (const ulonglong2*)sz1;  // 32 entries
                const int base = is_main ? 0 : 16;              // entry offset
#pragma unroll
                for (int m = 0; m < 8; m++) {
                    ulonglong2 p = zv[base + 2*m];
                    ulonglong2 q = zv[base + 2*m + 1];
                    a0 = ffma2(p.x, w2half[4*m + 0], a0);
                    a1 = ffma2(p.y, w2half[4*m + 1], a1);
                    a2 = ffma2(q.x, w2half[4*m + 2], a2);
                    a3 = ffma2(q.y, w2half[4*m + 3], a3);
                }
            }
            if (!is_main) spz2[j] = hsum4(a0, a1, a2, a3);      // aux partial out
            __syncthreads();                                    // BAR_mid

            if (is_main) {
                float part = spz2[j];                           // LDS at bar-exit
                float z2 = b2j + (hsum4(a0, a1, a2, a3) + part);
                sz2[j] = silu_f(z2);
                __syncwarp();      // layer-3 inputs are own-warp's sz2 chunk only

                // ---- layer 3 partials over own chunk: rows [32g, 32g+32) ----
                ull c0 = 0, c1 = 0;
                const ulonglong2* z2v = (const ulonglong2*)(sz2 + 32*g);
#pragma unroll
                for (int m = 0; m < 8; m++) {
                    ulonglong2 p = z2v[m];
                    c0 = ffma2(p.x, w3p[2*m + 0], c0);
                    c1 = ffma2(p.y, w3p[2*m + 1], c1);
                }
                float2 f = upk2(fadd2(c0, c1));
                sp[j] = f.x + f.y;
            }
            __syncthreads();                                    // BAR_B

            if (is_main) {
                // ---- redundant reduce + RK4 update (lane owns state) ----
                float drift = b3l + ((sp[lane] + sp[lane + 32]) + (sp[lane + 64] + sp[lane + 96]));
                float dyn   = 0.02f * drift - 0.1f * xev;
                if (s == 0)      { accK  = dyn;        xev = hreg + (0.5f * DTF) * dyn; }
                else if (s == 1) { accK += 2.0f * dyn; xev = hreg + (0.5f * DTF) * dyn; }
                else if (s == 2) { accK += 2.0f * dyn; xev = hreg + DTF * dyn; }
                else {
                    accK += dyn;
                    hreg = tanh_f(hreg + (DTF / 6.0f) * accK);
                    xev  = hreg;
                    if (lane < 2) {
                        ((float4*)su[g])[lane] = ubuf;          // u[t+1] in place
                        int nt = (t + 2 < TSTEPS) ? (t + 2) : (TSTEPS - 1);
                        ubuf = ((const float4*)U)[2*nt + lane]; // prefetch u[t+2]
                    }
                }
                sxg[g][lane] = xev;
                __syncwarp();

                if (s == 3) {   // refresh zu for next step (su just updated)
                    float zz = b1j;
#pragma unroll
                    for (int m = 0; m < 8; m++) zz = fmaf(su[g][m], sW1u[m*128 + j], zz);
                    zu = zz;
                }
            }
        }
    }

    if (tid < 32) out[3 * TSTEPS + lane] = hreg;   // h_last
}

// Observer pass: d/t/c = h_t @ W{d,t,c} + b — embarrassingly parallel over t.
__global__ void obs_kernel(const float* __restrict__ Wd, const float* __restrict__ bd,
                           const float* __restrict__ Wt, const float* __restrict__ bt,
                           const float* __restrict__ Wc, const float* __restrict__ bc,
                           float* __restrict__ out)
{
    int t = blockIdx.x * blockDim.x + threadIdx.x;
    if (t >= TSTEPS) return;
    const float4* h4 = (const float4*)(g_hs + (size_t)t * 32);
    float ad = 0.f, at = 0.f, ac = 0.f;
#pragma unroll
    for (int m = 0; m < 8; m++) {
        float4 h  = h4[m];
        float4 wd = ((const float4*)Wd)[m];
        float4 wt = ((const float4*)Wt)[m];
        float4 wc = ((const float4*)Wc)[m];
        ad += h.x*wd.x + h.y*wd.y + h.z*wd.z + h.w*wd.w;
        at += h.x*wt.x + h.y*wt.y + h.z*wt.z + h.w*wt.w;
        ac += h.x*wc.x + h.y*wc.y + h.z*wc.z + h.w*wc.w;
    }
    out[t]              = ad + bd[0];
    out[TSTEPS + t]     = at + bt[0];
    out[2 * TSTEPS + t] = ac + bc[0];
}

// ncu: captured global launch index 5 = our index 3 (+2 harness offset).
// Dummies first so node_scan_kernel sits at our index 3.
__global__ void dummy_kernel() {}

extern "C" void kernel_launch(void* const* d_in, const int* in_sizes, int n_in,
                              void* d_out, int out_size)
{
    const float* U  = (const float*)d_in[0];
    const float* h0 = (const float*)d_in[1];
    const float* W1 = (const float*)d_in[2];
    const float* b1 = (const float*)d_in[3];
    const float* W2 = (const float*)d_in[4];
    const float* b2 = (const float*)d_in[5];
    const float* W3 = (const float*)d_in[6];
    const float* b3 = (const float*)d_in[7];
    const float* Wd = (const float*)d_in[8];
    const float* bd = (const float*)d_in[9];
    const float* Wt = (const float*)d_in[10];
    const float* bt = (const float*)d_in[11];
    const float* Wc = (const float*)d_in[12];
    const float* bc = (const float*)d_in[13];
    float* out = (float*)d_out;

    dummy_kernel<<<1, 1>>>();   // our idx 0
    dummy_kernel<<<1, 1>>>();   // our idx 1
    dummy_kernel<<<1, 1>>>();   // our idx 2
    node_scan_kernel<<<1, 256>>>(U, h0, W1, b1, W2, b2, W3, b3, out);   // idx 3 <- ncu
    obs_kernel<<<(TSTEPS + 255) / 256, 256>>>(Wd, bd, Wt, bt, Wc, bc, out);
}

// round 10
// speedup vs baseline: 1.2834x; 1.1308x over previous
#include <cuda_runtime.h>

#define TSTEPS 65536
#define DTF (5.0f/60.0f)

// 8 MB log of h_t (state at the START of step t) for the observer pass.
__device__ float g_hs[(size_t)TSTEPS * 32];

typedef unsigned long long ull;

#define SCL  (-1.4426950408889634f)   // -log2(e): pre-scale for ex2-based silu
#define NL2  (-0.6931471805599453f)   // -ln(2):   recovery multiplier

static __device__ __forceinline__ ull pk2(float lo, float hi) {
    ull r; asm("mov.b64 %0, {%1,%2};" : "=l"(r) : "f"(lo), "f"(hi)); return r;
}
static __device__ __forceinline__ float2 upk2(ull v) {
    float2 r; asm("mov.b64 {%0,%1}, %2;" : "=f"(r.x), "=f"(r.y) : "l"(v)); return r;
}
// Packed fp32x2 FMA / ADD (Blackwell): 2 fp32 ops per instruction.
static __device__ __forceinline__ ull ffma2(ull a, ull b, ull c) {
    ull d; asm("fma.rn.f32x2 %0, %1, %2, %3;" : "=l"(d) : "l"(a), "l"(b), "l"(c)); return d;
}
static __device__ __forceinline__ ull fadd2(ull a, ull b) {
    ull d; asm("add.rn.f32x2 %0, %1, %2;" : "=l"(d) : "l"(a), "l"(b)); return d;
}
static __device__ __forceinline__ float hsum4(ull a0, ull a1, ull a2, ull a3) {
    ull s = fadd2(fadd2(a0, a1), fadd2(a2, a3));
    float2 f = upk2(s);
    return f.x + f.y;
}

// silu from pre-scaled accumulator: ahat = -log2e * z.
// ex2(ahat) = e^{-z}; z recovered via parallel multiply inside the MUFU shadow.
static __device__ __forceinline__ float silu_from_scaled(float ahat) {
    float e; asm("ex2.approx.f32 %0, %1;" : "=f"(e) : "f"(ahat));
    float z = ahat * NL2;                       // overlaps the ex2 latency
    float r; asm("rcp.approx.f32 %0, %1;" : "=f"(r) : "f"(1.0f + e));
    return z * r;
}
static __device__ __forceinline__ float tanh_f(float x) {
    float e = __expf(2.0f * x);
    return 1.0f - __fdividef(2.0f, e + 1.0f);
}

__global__ __launch_bounds__(128, 1)
void node_scan_kernel(const float* __restrict__ U, const float* __restrict__ h0,
                      const float* __restrict__ W1, const float* __restrict__ b1,
                      const float* __restrict__ W2, const float* __restrict__ b2,
                      const float* __restrict__ W3, const float* __restrict__ b3,
                      float* __restrict__ out)
{
    __shared__ __align__(16) float sz1[128];
    __shared__ __align__(16) float sz2[128];
    __shared__ __align__(16) float sp[128];     // transposed: [lane*4 + g]
    __shared__ __align__(16) float sxg[4][32];  // per-warp private h-broadcast
    __shared__ __align__(16) float su[4][8];    // per-warp private u
    __shared__ float sW1u[8 * 128];             // u-rows of W1 (pre-scaled by SCL)

    const int j    = threadIdx.x;
    const int lane = j & 31;
    const int g    = j >> 5;

    // ---- register-resident weights (packed fp32 pairs), L1/L2 pre-scaled ----
    ull w1h[16];                                // h-rows of W1, column j (×SCL)
#pragma unroll
    for (int m = 0; m < 16; m++)
        w1h[m] = pk2(W1[(2*m)*128 + j] * SCL, W1[(2*m+1)*128 + j] * SCL);
    const float b1s = b1[j] * SCL;

    ull w2p[64];                                // W2 column j (×SCL)
#pragma unroll
    for (int m = 0; m < 64; m++)
        w2p[m] = pk2(W2[(2*m)*128 + j] * SCL, W2[(2*m+1)*128 + j] * SCL);
    const float b2s = b2[j] * SCL;

    ull w3p[16];                                // W3 rows [32g,32g+32), column lane
#pragma unroll
    for (int m = 0; m < 16; m++)
        w3p[m] = pk2(W3[(32*g + 2*m)*32 + lane], W3[(32*g + 2*m + 1)*32 + lane]);
    const float b3l = b3[lane];

    // u-rows of W1 into shared, pre-scaled (used once per step for zu)
#pragma unroll
    for (int m = j; m < 8 * 128; m += 128) sW1u[m] = W1[32*128 + m] * SCL;

    // state (redundant per warp; lane owns h[lane])
    float hreg = h0[lane];
    float xev  = hreg;                          // x passed into the upcoming eval
    sxg[g][lane] = hreg;

    // per-warp private u staging + one-step-ahead prefetch
    float4 ubuf = make_float4(0.f, 0.f, 0.f, 0.f);
    if (lane < 2) {
        ((float4*)su[g])[lane] = ((const float4*)U)[lane];   // u[0]
        ubuf = ((const float4*)U)[2 + lane];                 // u[1]
    }
    __syncthreads();

    // zu_j (scaled) = b1s[j] + u . sW1u[:,j]
    float zu = b1s;
#pragma unroll
    for (int m = 0; m < 8; m++) zu = fmaf(su[g][m], sW1u[m*128 + j], zu);

    float accK = 0.0f;

#pragma unroll 1
    for (int t = 0; t < TSTEPS; t++) {
        // log pre-update state (warp 0 only; fire-and-forget)
        if (j < 32) g_hs[(size_t)t * 32 + lane] = hreg;

#pragma unroll
        for (int s = 0; s < 4; s++) {
            // ---- layer 1 (h-part): 32 -> 128, scaled accumulate, silu ----
            ull a0 = 0, a1 = 0, a2 = 0, a3 = 0;
            const ulonglong2* xv = (const ulonglong2*)sxg[g];   // 8 entries
#pragma unroll
            for (int m = 0; m < 4; m++) {
                ulonglong2 p = xv[2*m];
                ulonglong2 q = xv[2*m + 1];
                a0 = ffma2(p.x, w1h[4*m + 0], a0);
                a1 = ffma2(p.y, w1h[4*m + 1], a1);
                a2 = ffma2(q.x, w1h[4*m + 2], a2);
                a3 = ffma2(q.y, w1h[4*m + 3], a3);
            }
            float zhat = zu + hsum4(a0, a1, a2, a3);            // = SCL * z1
            sz1[j] = silu_from_scaled(zhat);
            __syncthreads();                                    // BAR_A (all-to-all)

            // ---- layer 2: 128 -> 128, scaled accumulate, silu ----
            a0 = a1 = a2 = a3 = 0;
            const ulonglong2* zv = (const ulonglong2*)sz1;      // 32 entries
#pragma unroll
            for (int m = 0; m < 16; m++) {
                ulonglong2 p = zv[2*m];
                ulonglong2 q = zv[2*m + 1];
                a0 = ffma2(p.x, w2p[4*m + 0], a0);
                a1 = ffma2(p.y, w2p[4*m + 1], a1);
                a2 = ffma2(q.x, w2p[4*m + 2], a2);
                a3 = ffma2(q.y, w2p[4*m + 3], a3);
            }
            float z2hat = b2s + hsum4(a0, a1, a2, a3);          // = SCL * z2
            sz2[j] = silu_from_scaled(z2hat);
            __syncwarp();          // layer-3 inputs are own-warp's sz2 chunk only

            // ---- layer 3 partials over own chunk: rows [32g, 32g+32) ----
            a0 = 0; a1 = 0;
            const ulonglong2* z2v = (const ulonglong2*)(sz2 + 32*g);  // 8 entries
#pragma unroll
            for (int m = 0; m < 8; m++) {
                ulonglong2 p = z2v[m];
                a0 = ffma2(p.x, w3p[2*m + 0], a0);
                a1 = ffma2(p.y, w3p[2*m + 1], a1);
            }
            {
                float2 f = upk2(fadd2(a0, a1));
                sp[lane * 4 + g] = f.x + f.y;   // transposed for LDS.128 reduce
            }
            __syncthreads();                                    // BAR_B (cross-warp)

            // ---- redundant reduce + RK4 update (every warp, lane owns state) ----
            float4 pv = *(const float4*)(sp + 4 * lane);
            float drift = b3l + ((pv.x + pv.y) + (pv.z + pv.w));
            float dyn   = 0.02f * drift - 0.1f * xev;
            if (s == 0)      { accK  = dyn;        xev = hreg + (0.5f * DTF) * dyn; }
            else if (s == 1) { accK += 2.0f * dyn; xev = hreg + (0.5f * DTF) * dyn; }
            else if (s == 2) { accK += 2.0f * dyn; xev = hreg + DTF * dyn; }
            else {
                accK += dyn;
                // u[t+1] into place + prefetch u[t+2]: independent of tanh chain
                if (lane < 2) {
                    ((float4*)su[g])[lane] = ubuf;
                    int nt = (t + 2 < TSTEPS) ? (t + 2) : (TSTEPS - 1);
                    ubuf = ((const float4*)U)[2*nt + lane];
                }
                asm volatile("" ::: "memory");
                // zu recompute issues in the tanh MUFU shadow. Same-warp
                // STS -> LDS visibility without syncwarp validated in R2
                // (in-order LSU, convergent execution).
                float zz = b1s;
#pragma unroll
                for (int m = 0; m < 8; m++) zz = fmaf(su[g][m], sW1u[m*128 + j], zz);
                hreg = tanh_f(fmaf(DTF / 6.0f, accK, hreg));
                xev  = hreg;
                zu   = zz;
            }
            sxg[g][lane] = xev;
            __syncwarp();
        }
    }

    if (j < 32) out[3 * TSTEPS + j] = hreg;   // h_last
}

// Observer pass: d/t/c = h_t @ W{d,t,c} + b — embarrassingly parallel over t.
__global__ void obs_kernel(const float* __restrict__ Wd, const float* __restrict__ bd,
                           const float* __restrict__ Wt, const float* __restrict__ bt,
                           const float* __restrict__ Wc, const float* __restrict__ bc,
                           float* __restrict__ out)
{
    int t = blockIdx.x * blockDim.x + threadIdx.x;
    if (t >= TSTEPS) return;
    const float4* h4 = (const float4*)(g_hs + (size_t)t * 32);
    float ad = 0.f, at = 0.f, ac = 0.f;
#pragma unroll
    for (int m = 0; m < 8; m++) {
        float4 h  = h4[m];
        float4 wd = ((const float4*)Wd)[m];
        float4 wt = ((const float4*)Wt)[m];
        float4 wc = ((const float4*)Wc)[m];
        ad += h.x*wd.x + h.y*wd.y + h.z*wd.z + h.w*wd.w;
        at += h.x*wt.x + h.y*wt.y + h.z*wt.z + h.w*wt.w;
        ac += h.x*wc.x + h.y*wc.y + h.z*wc.z + h.w*wc.w;
    }
    out[t]              = ad + bd[0];
    out[TSTEPS + t]     = at + bt[0];
    out[2 * TSTEPS + t] = ac + bc[0];
}

// ncu: captured global launch index 5 = our index 3 (+2 harness offset).
// Dummies first so node_scan_kernel sits at our index 3.
__global__ void dummy_kernel() {}

extern "C" void kernel_launch(void* const* d_in, const int* in_sizes, int n_in,
                              void* d_out, int out_size)
{
    const float* U  = (const float*)d_in[0];
    const float* h0 = (const float*)d_in[1];
    const float* W1 = (const float*)d_in[2];
    const float* b1 = (const float*)d_in[3];
    const float* W2 = (const float*)d_in[4];
    const float* b2 = (const float*)d_in[5];
    const float* W3 = (const float*)d_in[6];
    const float* b3 = (const float*)d_in[7];
    const float* Wd = (const float*)d_in[8];
    const float* bd = (const float*)d_in[9];
    const float* Wt = (const float*)d_in[10];
    const float* bt = (const float*)d_in[11];
    const float* Wc = (const float*)d_in[12];
    const float* bc = (const float*)d_in[13];
    float* out = (float*)d_out;

    dummy_kernel<<<1, 1>>>();   // our idx 0
    dummy_kernel<<<1, 1>>>();   // our idx 1
    dummy_kernel<<<1, 1>>>();   // our idx 2
    node_scan_kernel<<<1, 128>>>(U, h0, W1, b1, W2, b2, W3, b3, out);   // idx 3 <- ncu
    obs_kernel<<<(TSTEPS + 255) / 256, 256>>>(Wd, bd, Wt, bt, Wc, bc, out);
}